// round 16
// baseline (speedup 1.0000x reference)
#include <cuda_runtime.h>
#include <cuda_bf16.h>
#include <math.h>
#include <stdint.h>

#define BB 4
#define LL 5
#define NN 20      // B*L
#define CIN 64
#define HH 256
#define WW 128

// ---------------- scratch (device globals; no allocation) ----------------
__device__ __nv_bfloat16 g_nb[NN * CIN * HH * WW];   // bf16 sampled neigh (~84MB)
__device__ __nv_bfloat16 g_m1[NN * 32 * 128 * 64];   // conv1 out (bf16)
__device__ __nv_bfloat16 g_m2[NN * 64 * 64 * 32];    // conv2 out (bf16)
__device__ float         g_m3[NN * 64 * 32 * 16];    // conv3 out (f32, for pooling)
__device__ float         g_attn[NN];                 // softmax weights
// packed B fragments: [ic][ocg][lane][2] uint32
__device__ uint32_t g_wp1[64 * 4 * 32 * 2];
__device__ uint32_t g_wp2[32 * 8 * 32 * 2];
__device__ uint32_t g_wp3[64 * 8 * 32 * 2];

// ---------------- weight pack (device helper, folded into gridsample) -------------
__device__ __forceinline__ void pack_one(const float* w, uint32_t* dst,
                                         int IC, int OCG, int e) {
    int lane = e & 31;
    int ocg  = (e >> 5) % OCG;
    int ic   = (e >> 5) / OCG;
    int g = lane >> 2, t = lane & 3;
    int oc = ocg * 8 + g;
    const float* wb = w + ((size_t)oc * IC + ic) * 16;
    uint32_t l0 = __bfloat16_as_ushort(__float2bfloat16(wb[2 * t]));
    uint32_t h0 = __bfloat16_as_ushort(__float2bfloat16(wb[2 * t + 1]));
    uint32_t l1 = __bfloat16_as_ushort(__float2bfloat16(wb[2 * t + 8]));
    uint32_t h1 = __bfloat16_as_ushort(__float2bfloat16(wb[2 * t + 9]));
    int o = ((ic * OCG + ocg) * 32 + lane) * 2;
    dst[o]     = l0 | (h0 << 16);
    dst[o + 1] = l1 | (h1 << 16);
}

// ---------------- K1: affine grid sample -> bf16 (256 thr, 2-ch split) ------------
// Also performs weight packing in the first 128 blocks (conv1 runs strictly after).
__global__ void __launch_bounds__(256) k_gridsample(
        const float* __restrict__ x, const float* __restrict__ nam,
        const float* __restrict__ w1, const float* __restrict__ w2,
        const float* __restrict__ w3) {
    int n  = blockIdx.y;       // 0..19
    int yy = blockIdx.x;       // 0..255
    int tid = threadIdx.x;
    int c0 = tid >> 7;         // channel half 0/1
    int xx = tid & 127;

    // fold pack work (32768 entries over first 128 blocks of row n==0)
    if (n == 0 && blockIdx.x < 128) {
        int idx = blockIdx.x * 256 + tid;
        if (idx < 8192)        pack_one(w1, g_wp1, 64, 4, idx);
        else if (idx < 16384)  pack_one(w2, g_wp2, 32, 8, idx - 8192);
        else                   pack_one(w3, g_wp3, 64, 8, idx - 16384);
    }

    int b = n / LL, nl = n % LL;
    const float* t = nam + ((size_t)(b * LL * LL) + nl) * 6;   // nam[b][0][nl]
    float t00 = t[0], t01 = t[1], t02 = t[2];
    float t10 = t[3], t11 = t[4], t12 = t[5];

    float gx = (xx + 0.5f) * (2.0f / WW) - 1.0f;
    float gy = (yy + 0.5f) * (2.0f / HH) - 1.0f;
    float sx = (((t00 * gx + t01 * gy + t02) + 1.0f) * WW - 1.0f) * 0.5f;
    float sy = (((t10 * gx + t11 * gy + t12) + 1.0f) * HH - 1.0f) * 0.5f;
    float x0f = floorf(sx), y0f = floorf(sy);
    int ix0 = (int)x0f, iy0 = (int)y0f;
    int ix1 = ix0 + 1, iy1 = iy0 + 1;
    float wx1 = sx - x0f, wx0 = 1.0f - wx1;
    float wy1 = sy - y0f, wy0 = 1.0f - wy1;
    bool vx0 = (ix0 >= 0) && (ix0 < WW), vx1 = (ix1 >= 0) && (ix1 < WW);
    bool vy0 = (iy0 >= 0) && (iy0 < HH), vy1 = (iy1 >= 0) && (iy1 < HH);
    float w00 = wx0 * wy0 * ((vx0 && vy0) ? 1.f : 0.f);
    float w10 = wx1 * wy0 * ((vx1 && vy0) ? 1.f : 0.f);
    float w01 = wx0 * wy1 * ((vx0 && vy1) ? 1.f : 0.f);
    float w11 = wx1 * wy1 * ((vx1 && vy1) ? 1.f : 0.f);
    int cx0 = min(max(ix0, 0), WW - 1), cx1 = min(max(ix1, 0), WW - 1);
    int cy0 = min(max(iy0, 0), HH - 1), cy1 = min(max(iy1, 0), HH - 1);

    size_t base = (size_t)n * CIN * HH * WW;
    int o00 = cy0 * WW + cx0, o10 = cy0 * WW + cx1;
    int o01 = cy1 * WW + cx0, o11 = cy1 * WW + cx1;
    size_t ob = base + (size_t)yy * WW + xx;
    #pragma unroll 4
    for (int c = c0; c < CIN; c += 2) {
        const float* p = x + base + (size_t)c * (HH * WW);
        float v = w00 * p[o00] + w10 * p[o10] + w01 * p[o01] + w11 * p[o11];
        g_nb[ob + (size_t)c * (HH * WW)] = __float2bfloat16(v);
    }
}

// ---------------- conv: cp.async-pipelined implicit GEMM, mma m16n8k16 bf16 -------
// Block = NTHR thr (NTHR/32 warps); each warp computes one 16-px m-tile x OCG ocg.
// Input staged aligned (stride WA+2, zero pad cols); unaligned A pairs built at
// consume time via 2 LDS + PRMT. Double-buffered cp.async, 2 syncs/chunk.
template<int NTHR, int IC, int OCGT, int OCG, int IH, int IW, int ROWS, int CH, int LAYER>
__global__ void __launch_bounds__(NTHR) k_conv(const float* __restrict__ bias) {
    constexpr int OH  = IH / 2, OW = IW / 2;
    constexpr int R_IN = 2 * ROWS + 2;
    constexpr int WA  = IW / 2;          // aligned words per row (pow2)
    constexpr int WAP = WA + 2;          // +2 zero pad cols
    constexpr int NCH = IC / CH;
    constexpr int DATA_W = CH * R_IN * WA;       // words per chunk
    constexpr int ND   = DATA_W / NTHR;
    constexpr int BW   = CH * OCG * 64;          // B words per chunk
    constexpr int NB_IT = BW / (NTHR * 4);
    static_assert(CH * OCG == 32, "B staging assumes CH*OCG==32");
    static_assert(DATA_W % NTHR == 0 && BW % (NTHR * 4) == 0, "staging divisibility");
    static_assert((NTHR / 32) * 16 == ROWS * OW, "m-tile coverage");

    __shared__ __align__(16) uint32_t sA[2][CH * R_IN * WAP];
    __shared__ __align__(16) uint32_t sB[2][BW];

    const __nv_bfloat16* in = (LAYER == 1) ? g_nb : (LAYER == 2) ? g_m1 : g_m2;
    const uint32_t* wpack   = (LAYER == 1) ? g_wp1 : (LAYER == 2) ? g_wp2 : g_wp3;

    int n   = blockIdx.y;
    int oy0 = blockIdx.x * ROWS;
    int zb  = blockIdx.z * OCG;
    int tid = threadIdx.x;
    int wid = tid >> 5, lane = tid & 31;
    int g = lane >> 2, t = lane & 3;
    int ky0 = t >> 1, kxp = t & 1;
    int ry  = (wid * 16) / OW;
    int wox = (wid * 16) % OW;
    int iy0 = 2 * oy0 - 1;
    int PP  = (2 * ry + ky0) * WAP + wox + g + kxp;   // a0 word idx (incl. pad shift)
    int PP2 = PP + 2 * WAP;

    const uint32_t* in32 = reinterpret_cast<const uint32_t*>(in)
                         + (size_t)n * IC * IH * WA;

    uint32_t saAddr[2], sbAddr[2];
    saAddr[0] = (uint32_t)__cvta_generic_to_shared(&sA[0][0]);
    saAddr[1] = (uint32_t)__cvta_generic_to_shared(&sA[1][0]);
    sbAddr[0] = (uint32_t)__cvta_generic_to_shared(&sB[0][0]);
    sbAddr[1] = (uint32_t)__cvta_generic_to_shared(&sB[1][0]);

    // zero the pad columns of both buffers (written once, never overwritten)
    for (int i = tid; i < 4 * CH * R_IN; i += NTHR) {
        int bufn = i & 1, side = (i >> 1) & 1, row = i >> 2;
        sA[bufn][row * WAP + (side ? WA + 1 : 0)] = 0;
    }

    float4 acc[OCG];
    #pragma unroll
    for (int i = 0; i < OCG; i++) acc[i] = make_float4(0.f, 0.f, 0.f, 0.f);

    // ---- cp.async stage of one chunk ----
    auto stage = [&](int ic0, int bufn) {
        #pragma unroll
        for (int it = 0; it < ND; it++) {
            int j = tid + it * NTHR;
            int icl = j / (R_IN * WA);
            int rem = j - icl * (R_IN * WA);
            int r = rem >> (WA == 64 ? 6 : (WA == 32 ? 5 : 4));
            int q = rem & (WA - 1);
            int iy = iy0 + r;
            int v = (iy >= 0 && iy < IH) ? 4 : 0;
            const uint32_t* src = in32 + (((size_t)(ic0 + icl) * IH
                                  + (v ? iy : 0)) * WA + q);
            uint32_t dst = saAddr[bufn] + (uint32_t)(((icl * R_IN + r) * WAP + 1 + q) << 2);
            asm volatile("cp.async.ca.shared.global [%0], [%1], 4, %2;"
                         :: "r"(dst), "l"(src), "r"(v));
        }
        #pragma unroll
        for (int it = 0; it < NB_IT; it++) {
            int u = tid + it * NTHR;
            int icl = u / (OCG * 16);
            int rem = u - icl * (OCG * 16);
            const uint32_t* src = wpack + (((size_t)(ic0 + icl) * OCGT + zb) * 64
                                  + rem * 4);
            uint32_t dst = sbAddr[bufn] + (uint32_t)((icl * OCG * 64 + rem * 4) << 2);
            asm volatile("cp.async.cg.shared.global [%0], [%1], 16;"
                         :: "r"(dst), "l"(src));
        }
        asm volatile("cp.async.commit_group;");
    };

    stage(0, 0);

    for (int cc = 0; cc < NCH; cc++) {
        int cb = cc & 1;
        if (cc + 1 < NCH) {
            stage((cc + 1) * CH, 1 - cb);
            asm volatile("cp.async.wait_group 1;");
        } else {
            asm volatile("cp.async.wait_group 0;");
        }
        __syncthreads();                       // buf[cb] ready for everyone

        const uint32_t* ra = &sA[cb][0];
        #pragma unroll
        for (int icl = 0; icl < CH; icl++) {
            const uint32_t* rr = ra + icl * R_IN * WAP;
            uint32_t wa0 = rr[PP],      wa1 = rr[PP + 1];
            uint32_t wa2 = rr[PP + 8],  wa3 = rr[PP + 9];
            uint32_t wb0 = rr[PP2],     wb1 = rr[PP2 + 1];
            uint32_t wb2 = rr[PP2 + 8], wb3 = rr[PP2 + 9];
            uint32_t a0 = __byte_perm(wa0, wa1, 0x5432);
            uint32_t a1 = __byte_perm(wa2, wa3, 0x5432);
            uint32_t a2 = __byte_perm(wb0, wb1, 0x5432);
            uint32_t a3 = __byte_perm(wb2, wb3, 0x5432);
            // B fragments: 8B-aligned pairs -> LDS.64
            const uint2* bp2 = reinterpret_cast<const uint2*>(&sB[cb][icl * OCG * 64])
                             + lane;
            #pragma unroll
            for (int ocg = 0; ocg < OCG; ocg++) {
                uint2 bv = bp2[ocg * 32];
                asm volatile(
                    "mma.sync.aligned.m16n8k16.row.col.f32.bf16.bf16.f32 "
                    "{%0,%1,%2,%3}, {%4,%5,%6,%7}, {%8,%9}, {%0,%1,%2,%3};\n"
                    : "+f"(acc[ocg].x), "+f"(acc[ocg].y),
                      "+f"(acc[ocg].z), "+f"(acc[ocg].w)
                    : "r"(a0), "r"(a1), "r"(a2), "r"(a3), "r"(bv.x), "r"(bv.y));
            }
        }
        __syncthreads();                       // safe to overwrite buf[cb]
    }

    // epilogue: C frag rows (g, g+8) = px (wox+g, wox+g+8), cols oc0, oc0+1
    const size_t plane = (size_t)OH * OW;
    int oy = oy0 + ry;
    int ox = wox + g;
    #pragma unroll
    for (int ocg = 0; ocg < OCG; ocg++) {
        int oc0 = (zb + ocg) * 8 + 2 * t;
        float bv0 = bias[oc0], bv1 = bias[oc0 + 1];
        size_t base0 = ((size_t)n * (OCGT * 8) + oc0) * plane + (size_t)oy * OW;
        float v00 = fmaxf(acc[ocg].x + bv0, 0.f);
        float v01 = fmaxf(acc[ocg].y + bv1, 0.f);
        float v10 = fmaxf(acc[ocg].z + bv0, 0.f);
        float v11 = fmaxf(acc[ocg].w + bv1, 0.f);
        if (LAYER == 3) {
            g_m3[base0 + ox]             = v00;
            g_m3[base0 + plane + ox]     = v01;
            g_m3[base0 + ox + 8]         = v10;
            g_m3[base0 + plane + ox + 8] = v11;
        } else if (LAYER == 2) {
            g_m2[base0 + ox]             = __float2bfloat16(v00);
            g_m2[base0 + plane + ox]     = __float2bfloat16(v01);
            g_m2[base0 + ox + 8]         = __float2bfloat16(v10);
            g_m2[base0 + plane + ox + 8] = __float2bfloat16(v11);
        } else {
            g_m1[base0 + ox]             = __float2bfloat16(v00);
            g_m1[base0 + plane + ox]     = __float2bfloat16(v01);
            g_m1[base0 + ox + 8]         = __float2bfloat16(v10);
            g_m1[base0 + plane + ox + 8] = __float2bfloat16(v11);
        }
    }
}

// ---------------- K5: pool + key/qry MLPs + attention softmax ----------------
__global__ void k_attn(const float* __restrict__ k1w, const float* __restrict__ k1b,
                       const float* __restrict__ k2w, const float* __restrict__ k2b,
                       const float* __restrict__ k3w, const float* __restrict__ k3b,
                       const float* __restrict__ q1w, const float* __restrict__ q1b,
                       const float* __restrict__ q2w, const float* __restrict__ q2b,
                       const float* __restrict__ q3w, const float* __restrict__ q3b,
                       const float* __restrict__ aw,  const float* __restrict__ ab) {
    int b = blockIdx.x;
    int tid = threadIdx.x;
    int warp = tid >> 5, lane = tid & 31;
    __shared__ float s_pool[5][64];
    __shared__ float s_key[5][256];
    __shared__ float s_h1[256];
    __shared__ float s_h2[128];
    __shared__ float s_qry[32];
    __shared__ float s_q[256];
    __shared__ float s_log[5];

    for (int tk = warp; tk < 5 * 64; tk += 8) {
        int j = tk >> 6, c = tk & 63;
        const float* p = g_m3 + ((size_t)((b * 5 + j) * 64 + c)) * 512;
        float s = 0.f;
        for (int k = lane; k < 512; k += 32) s += p[k];
        #pragma unroll
        for (int o = 16; o; o >>= 1) s += __shfl_xor_sync(0xFFFFFFFFu, s, o);
        if (lane == 0) s_pool[j][c] = s * (1.0f / 512.0f);
    }
    __syncthreads();

    for (int j = 0; j < 5; j++) {
        {   float a = k1b[tid];
            #pragma unroll 8
            for (int c = 0; c < 64; c++) a += s_pool[j][c] * k1w[tid * 64 + c];
            s_h1[tid] = fmaxf(a, 0.f); }
        __syncthreads();
        if (tid < 128) {
            float a = k2b[tid];
            #pragma unroll 8
            for (int c = 0; c < 256; c++) a += s_h1[c] * k2w[tid * 256 + c];
            s_h2[tid] = fmaxf(a, 0.f);
        }
        __syncthreads();
        {   float a = k3b[tid];
            #pragma unroll 8
            for (int c = 0; c < 128; c++) a += s_h2[c] * k3w[tid * 128 + c];
            s_key[j][tid] = a; }
        __syncthreads();
    }

    {   float a = q1b[tid];
        #pragma unroll 8
        for (int c = 0; c < 64; c++) a += s_pool[0][c] * q1w[tid * 64 + c];
        s_h1[tid] = fmaxf(a, 0.f); }
    __syncthreads();
    if (tid < 128) {
        float a = q2b[tid];
        #pragma unroll 8
        for (int c = 0; c < 256; c++) a += s_h1[c] * q2w[tid * 256 + c];
        s_h2[tid] = fmaxf(a, 0.f);
    }
    __syncthreads();
    if (tid < 32) {
        float a = q3b[tid];
        #pragma unroll 8
        for (int c = 0; c < 128; c++) a += s_h2[c] * q3w[tid * 128 + c];
        s_qry[tid] = a;
    }
    __syncthreads();
    {   float a = ab[tid];
        #pragma unroll
        for (int m = 0; m < 32; m++) a += s_qry[m] * aw[tid * 32 + m];
        s_q[tid] = a; }
    __syncthreads();

    if (warp < 5) {
        float s = 0.f;
        for (int k = lane; k < 256; k += 32) s += s_key[warp][k] * s_q[k];
        #pragma unroll
        for (int o = 16; o; o >>= 1) s += __shfl_xor_sync(0xFFFFFFFFu, s, o);
        if (lane == 0) s_log[warp] = s;
    }
    __syncthreads();
    if (tid == 0) {
        float mx = s_log[0];
        #pragma unroll
        for (int j = 1; j < 5; j++) mx = fmaxf(mx, s_log[j]);
        float e[5], sum = 0.f;
        #pragma unroll
        for (int j = 0; j < 5; j++) { e[j] = __expf(s_log[j] - mx); sum += e[j]; }
        float inv = 1.0f / sum;
        #pragma unroll
        for (int j = 0; j < 5; j++) g_attn[b * 5 + j] = e[j] * inv;
    }
}

// ---------------- K6: fused bilinear-resample + weighted sum (256 thr, 2-ch) ------
__global__ void __launch_bounds__(256) k_fuse(
        const float* __restrict__ x, const float* __restrict__ nam,
        float* __restrict__ out) {
    int b  = blockIdx.y;
    int yy = blockIdx.x;
    int tid = threadIdx.x;
    int c0 = tid >> 7;
    int xx = tid & 127;

    float W00[5], W10[5], W01[5], W11[5];
    int   O00[5], O10[5], O01[5], O11[5];
    float gx = (xx + 0.5f) * (2.0f / WW) - 1.0f;
    float gy = (yy + 0.5f) * (2.0f / HH) - 1.0f;
    #pragma unroll
    for (int j = 0; j < 5; j++) {
        float a = g_attn[b * 5 + j];
        const float* t = nam + ((size_t)(b * LL * LL) + j) * 6;
        float sx = (((t[0] * gx + t[1] * gy + t[2]) + 1.0f) * WW - 1.0f) * 0.5f;
        float sy = (((t[3] * gx + t[4] * gy + t[5]) + 1.0f) * HH - 1.0f) * 0.5f;
        float x0f = floorf(sx), y0f = floorf(sy);
        int ix0 = (int)x0f, iy0 = (int)y0f;
        int ix1 = ix0 + 1, iy1 = iy0 + 1;
        float wx1 = sx - x0f, wx0 = 1.0f - wx1;
        float wy1 = sy - y0f, wy0 = 1.0f - wy1;
        bool vx0 = (ix0 >= 0) && (ix0 < WW), vx1 = (ix1 >= 0) && (ix1 < WW);
        bool vy0 = (iy0 >= 0) && (iy0 < HH), vy1 = (iy1 >= 0) && (iy1 < HH);
        W00[j] = a * wx0 * wy0 * ((vx0 && vy0) ? 1.f : 0.f);
        W10[j] = a * wx1 * wy0 * ((vx1 && vy0) ? 1.f : 0.f);
        W01[j] = a * wx0 * wy1 * ((vx0 && vy1) ? 1.f : 0.f);
        W11[j] = a * wx1 * wy1 * ((vx1 && vy1) ? 1.f : 0.f);
        int cx0 = min(max(ix0, 0), WW - 1), cx1 = min(max(ix1, 0), WW - 1);
        int cy0 = min(max(iy0, 0), HH - 1), cy1 = min(max(iy1, 0), HH - 1);
        O00[j] = cy0 * WW + cx0; O10[j] = cy0 * WW + cx1;
        O01[j] = cy1 * WW + cx0; O11[j] = cy1 * WW + cx1;
    }

    for (int c = c0; c < CIN; c += 2) {
        float acc = 0.f;
        #pragma unroll
        for (int j = 0; j < 5; j++) {
            const float* p = x + ((size_t)((b * 5 + j) * CIN) + c) * (HH * WW);
            acc += W00[j] * p[O00[j]] + W10[j] * p[O10[j]]
                 + W01[j] * p[O01[j]] + W11[j] * p[O11[j]];
        }
        out[((size_t)(b * CIN + c) * HH + yy) * WW + xx] = acc;
    }
}

// ---------------- launch ----------------
extern "C" void kernel_launch(void* const* d_in, const int* in_sizes, int n_in,
                              void* d_out, int out_size) {
    const float* x    = (const float*)d_in[0];
    // d_in[1] = record_len (int32) — unused (reference ignores it, all = L)
    const float* nam  = (const float*)d_in[2];
    const float* c1w  = (const float*)d_in[3];
    const float* c1b  = (const float*)d_in[4];
    const float* c2w  = (const float*)d_in[5];
    const float* c2b  = (const float*)d_in[6];
    const float* c3w  = (const float*)d_in[7];
    const float* c3b  = (const float*)d_in[8];
    const float* k1w  = (const float*)d_in[9];
    const float* k1b  = (const float*)d_in[10];
    const float* k2w  = (const float*)d_in[11];
    const float* k2b  = (const float*)d_in[12];
    const float* k3w  = (const float*)d_in[13];
    const float* k3b  = (const float*)d_in[14];
    const float* q1w  = (const float*)d_in[15];
    const float* q1b  = (const float*)d_in[16];
    const float* q2w  = (const float*)d_in[17];
    const float* q2b  = (const float*)d_in[18];
    const float* q3w  = (const float*)d_in[19];
    const float* q3b  = (const float*)d_in[20];
    const float* aw   = (const float*)d_in[21];
    const float* abv  = (const float*)d_in[22];
    float* out = (float*)d_out;

    k_gridsample<<<dim3(HH, NN), 256>>>(x, nam, c1w, c2w, c3w);
    //      NTHR IC OCGT OCG  IH   IW ROWS CH LAYER
    k_conv<256, 64,  4,  4, 256, 128,  2,  8, 1><<<dim3(64, NN, 1), 256>>>(c1b);
    k_conv<128, 32,  8,  4, 128,  64,  2,  8, 2><<<dim3(16, NN, 2), 128>>>(c2b);
    k_conv<128, 64,  8,  4,  64,  32,  4,  8, 3><<<dim3( 8, NN, 2), 128>>>(c3b);
    k_attn<<<BB, 256>>>(k1w, k1b, k2w, k2b, k3w, k3b,
                        q1w, q1b, q2w, q2b, q3w, q3b, aw, abv);
    k_fuse<<<dim3(HH, BB), 256>>>(x, nam, out);
}

// round 17
// speedup vs baseline: 1.1999x; 1.1999x over previous
#include <cuda_runtime.h>
#include <cuda_bf16.h>
#include <math.h>
#include <stdint.h>

#define BB 4
#define LL 5
#define NN 20      // B*L
#define CIN 64
#define HH 256
#define WW 128

// ---------------- scratch (device globals; no allocation) ----------------
__device__ float         g_neigh[NN * CIN * HH * WW]; // f32 sampled neigh (~168MB)
__device__ __nv_bfloat16 g_nb[NN * CIN * HH * WW];   // bf16 sampled neigh (~84MB)
__device__ __nv_bfloat16 g_m1[NN * 32 * 128 * 64];   // conv1 out (bf16)
__device__ __nv_bfloat16 g_m2[NN * 64 * 64 * 32];    // conv2 out (bf16)
__device__ float         g_m3[NN * 64 * 32 * 16];    // conv3 out (f32, for pooling)
__device__ float         g_attn[NN];                 // softmax weights
// packed B fragments: [ic][ocg][lane][2] uint32
__device__ uint32_t g_wp1[64 * 4 * 32 * 2];
__device__ uint32_t g_wp2[32 * 8 * 32 * 2];
__device__ uint32_t g_wp3[64 * 8 * 32 * 2];

// ---------------- K0: pack conv weights into mma B-fragment layout ----------------
__device__ __forceinline__ void pack_one(const float* w, uint32_t* dst,
                                         int IC, int OCG, int e) {
    int lane = e & 31;
    int ocg  = (e >> 5) % OCG;
    int ic   = (e >> 5) / OCG;
    int g = lane >> 2, t = lane & 3;
    int oc = ocg * 8 + g;
    const float* wb = w + ((size_t)oc * IC + ic) * 16;
    uint32_t l0 = __bfloat16_as_ushort(__float2bfloat16(wb[2 * t]));
    uint32_t h0 = __bfloat16_as_ushort(__float2bfloat16(wb[2 * t + 1]));
    uint32_t l1 = __bfloat16_as_ushort(__float2bfloat16(wb[2 * t + 8]));
    uint32_t h1 = __bfloat16_as_ushort(__float2bfloat16(wb[2 * t + 9]));
    int o = ((ic * OCG + ocg) * 32 + lane) * 2;
    dst[o]     = l0 | (h0 << 16);
    dst[o + 1] = l1 | (h1 << 16);
}

__global__ void k_pack(const float* __restrict__ w1, const float* __restrict__ w2,
                       const float* __restrict__ w3) {
    int idx = blockIdx.x * 256 + threadIdx.x;   // 32768 entries total
    if (idx < 8192)            pack_one(w1, g_wp1, 64, 4, idx);
    else if (idx < 16384)      pack_one(w2, g_wp2, 32, 8, idx - 8192);
    else if (idx < 32768)      pack_one(w3, g_wp3, 64, 8, idx - 16384);
}

// ---------------- K1: affine grid sample -> bf16 + f32 (1 px/thread) --------------
__global__ void k_gridsample(const float* __restrict__ x, const float* __restrict__ nam) {
    int n  = blockIdx.y;       // 0..19
    int yy = blockIdx.x;       // 0..255
    int xx = threadIdx.x;      // 0..127
    int b = n / LL, nl = n % LL;
    const float* t = nam + ((size_t)(b * LL * LL) + nl) * 6;   // nam[b][0][nl]
    float t00 = t[0], t01 = t[1], t02 = t[2];
    float t10 = t[3], t11 = t[4], t12 = t[5];

    float gx = (xx + 0.5f) * (2.0f / WW) - 1.0f;
    float gy = (yy + 0.5f) * (2.0f / HH) - 1.0f;
    float sx = (((t00 * gx + t01 * gy + t02) + 1.0f) * WW - 1.0f) * 0.5f;
    float sy = (((t10 * gx + t11 * gy + t12) + 1.0f) * HH - 1.0f) * 0.5f;
    float x0f = floorf(sx), y0f = floorf(sy);
    int ix0 = (int)x0f, iy0 = (int)y0f;
    int ix1 = ix0 + 1, iy1 = iy0 + 1;
    float wx1 = sx - x0f, wx0 = 1.0f - wx1;
    float wy1 = sy - y0f, wy0 = 1.0f - wy1;
    bool vx0 = (ix0 >= 0) && (ix0 < WW), vx1 = (ix1 >= 0) && (ix1 < WW);
    bool vy0 = (iy0 >= 0) && (iy0 < HH), vy1 = (iy1 >= 0) && (iy1 < HH);
    float w00 = wx0 * wy0 * ((vx0 && vy0) ? 1.f : 0.f);
    float w10 = wx1 * wy0 * ((vx1 && vy0) ? 1.f : 0.f);
    float w01 = wx0 * wy1 * ((vx0 && vy1) ? 1.f : 0.f);
    float w11 = wx1 * wy1 * ((vx1 && vy1) ? 1.f : 0.f);
    int cx0 = min(max(ix0, 0), WW - 1), cx1 = min(max(ix1, 0), WW - 1);
    int cy0 = min(max(iy0, 0), HH - 1), cy1 = min(max(iy1, 0), HH - 1);

    size_t base = (size_t)n * CIN * HH * WW;
    int o00 = cy0 * WW + cx0, o10 = cy0 * WW + cx1;
    int o01 = cy1 * WW + cx0, o11 = cy1 * WW + cx1;
    size_t ob = base + (size_t)yy * WW + xx;
    #pragma unroll 4
    for (int c = 0; c < CIN; c++) {
        const float* p = x + base + (size_t)c * (HH * WW);
        float v = w00 * p[o00] + w10 * p[o10] + w01 * p[o01] + w11 * p[o11];
        size_t oo = ob + (size_t)c * (HH * WW);
        g_nb[oo]    = __float2bfloat16(v);
        g_neigh[oo] = v;
    }
}

// ---------------- conv: cp.async-pipelined implicit GEMM, mma m16n8k16 bf16 -------
// Block = NTHR thr (NTHR/32 warps); each warp computes one 16-px m-tile x OCG ocg.
// Input staged aligned (stride WA+2, zero pad cols); unaligned A pairs built at
// consume time via 2 LDS + PRMT. Double-buffered cp.async, 2 syncs/chunk.
template<int NTHR, int IC, int OCGT, int OCG, int IH, int IW, int ROWS, int CH, int LAYER>
__global__ void __launch_bounds__(NTHR) k_conv(const float* __restrict__ bias) {
    constexpr int OH  = IH / 2, OW = IW / 2;
    constexpr int R_IN = 2 * ROWS + 2;
    constexpr int WA  = IW / 2;          // aligned words per row (pow2)
    constexpr int WAP = WA + 2;          // +2 zero pad cols
    constexpr int NCH = IC / CH;
    constexpr int DATA_W = CH * R_IN * WA;       // words per chunk
    constexpr int ND   = DATA_W / NTHR;
    constexpr int BW   = CH * OCG * 64;          // B words per chunk
    constexpr int NB_IT = BW / (NTHR * 4);
    static_assert(CH * OCG == 32, "B staging assumes CH*OCG==32");
    static_assert(DATA_W % NTHR == 0 && BW % (NTHR * 4) == 0, "staging divisibility");
    static_assert((NTHR / 32) * 16 == ROWS * OW, "m-tile coverage");

    __shared__ __align__(16) uint32_t sA[2][CH * R_IN * WAP];
    __shared__ __align__(16) uint32_t sB[2][BW];

    const __nv_bfloat16* in = (LAYER == 1) ? g_nb : (LAYER == 2) ? g_m1 : g_m2;
    const uint32_t* wpack   = (LAYER == 1) ? g_wp1 : (LAYER == 2) ? g_wp2 : g_wp3;

    int n   = blockIdx.y;
    int oy0 = blockIdx.x * ROWS;
    int zb  = blockIdx.z * OCG;
    int tid = threadIdx.x;
    int wid = tid >> 5, lane = tid & 31;
    int g = lane >> 2, t = lane & 3;
    int ky0 = t >> 1, kxp = t & 1;
    int ry  = (wid * 16) / OW;
    int wox = (wid * 16) % OW;
    int iy0 = 2 * oy0 - 1;
    int PP  = (2 * ry + ky0) * WAP + wox + g + kxp;   // a0 word idx (incl. pad shift)
    int PP2 = PP + 2 * WAP;

    const uint32_t* in32 = reinterpret_cast<const uint32_t*>(in)
                         + (size_t)n * IC * IH * WA;

    uint32_t saAddr[2], sbAddr[2];
    saAddr[0] = (uint32_t)__cvta_generic_to_shared(&sA[0][0]);
    saAddr[1] = (uint32_t)__cvta_generic_to_shared(&sA[1][0]);
    sbAddr[0] = (uint32_t)__cvta_generic_to_shared(&sB[0][0]);
    sbAddr[1] = (uint32_t)__cvta_generic_to_shared(&sB[1][0]);

    // zero the pad columns of both buffers (written once, never overwritten)
    for (int i = tid; i < 4 * CH * R_IN; i += NTHR) {
        int bufn = i & 1, side = (i >> 1) & 1, row = i >> 2;
        sA[bufn][row * WAP + (side ? WA + 1 : 0)] = 0;
    }

    float4 acc[OCG];
    #pragma unroll
    for (int i = 0; i < OCG; i++) acc[i] = make_float4(0.f, 0.f, 0.f, 0.f);

    // ---- cp.async stage of one chunk ----
    auto stage = [&](int ic0, int bufn) {
        #pragma unroll
        for (int it = 0; it < ND; it++) {
            int j = tid + it * NTHR;
            int icl = j / (R_IN * WA);
            int rem = j - icl * (R_IN * WA);
            int r = rem >> (WA == 64 ? 6 : (WA == 32 ? 5 : 4));
            int q = rem & (WA - 1);
            int iy = iy0 + r;
            int v = (iy >= 0 && iy < IH) ? 4 : 0;
            const uint32_t* src = in32 + (((size_t)(ic0 + icl) * IH
                                  + (v ? iy : 0)) * WA + q);
            uint32_t dst = saAddr[bufn] + (uint32_t)(((icl * R_IN + r) * WAP + 1 + q) << 2);
            asm volatile("cp.async.ca.shared.global [%0], [%1], 4, %2;"
                         :: "r"(dst), "l"(src), "r"(v));
        }
        #pragma unroll
        for (int it = 0; it < NB_IT; it++) {
            int u = tid + it * NTHR;
            int icl = u / (OCG * 16);
            int rem = u - icl * (OCG * 16);
            const uint32_t* src = wpack + (((size_t)(ic0 + icl) * OCGT + zb) * 64
                                  + rem * 4);
            uint32_t dst = sbAddr[bufn] + (uint32_t)((icl * OCG * 64 + rem * 4) << 2);
            asm volatile("cp.async.cg.shared.global [%0], [%1], 16;"
                         :: "r"(dst), "l"(src));
        }
        asm volatile("cp.async.commit_group;");
    };

    stage(0, 0);

    for (int cc = 0; cc < NCH; cc++) {
        int cb = cc & 1;
        if (cc + 1 < NCH) {
            stage((cc + 1) * CH, 1 - cb);
            asm volatile("cp.async.wait_group 1;");
        } else {
            asm volatile("cp.async.wait_group 0;");
        }
        __syncthreads();                       // buf[cb] ready for everyone

        const uint32_t* ra = &sA[cb][0];
        const uint32_t* rw = &sB[cb][0];
        #pragma unroll
        for (int icl = 0; icl < CH; icl++) {
            const uint32_t* rr = ra + icl * R_IN * WAP;
            uint32_t wa0 = rr[PP],      wa1 = rr[PP + 1];
            uint32_t wa2 = rr[PP + 8],  wa3 = rr[PP + 9];
            uint32_t wb0 = rr[PP2],     wb1 = rr[PP2 + 1];
            uint32_t wb2 = rr[PP2 + 8], wb3 = rr[PP2 + 9];
            uint32_t a0 = __byte_perm(wa0, wa1, 0x5432);
            uint32_t a1 = __byte_perm(wa2, wa3, 0x5432);
            uint32_t a2 = __byte_perm(wb0, wb1, 0x5432);
            uint32_t a3 = __byte_perm(wb2, wb3, 0x5432);
            const uint32_t* bp = rw + icl * OCG * 64 + lane * 2;
            #pragma unroll
            for (int ocg = 0; ocg < OCG; ocg++) {
                uint32_t b0 = bp[ocg * 64], b1 = bp[ocg * 64 + 1];
                asm volatile(
                    "mma.sync.aligned.m16n8k16.row.col.f32.bf16.bf16.f32 "
                    "{%0,%1,%2,%3}, {%4,%5,%6,%7}, {%8,%9}, {%0,%1,%2,%3};\n"
                    : "+f"(acc[ocg].x), "+f"(acc[ocg].y),
                      "+f"(acc[ocg].z), "+f"(acc[ocg].w)
                    : "r"(a0), "r"(a1), "r"(a2), "r"(a3), "r"(b0), "r"(b1));
            }
        }
        __syncthreads();                       // safe to overwrite buf[cb]
    }

    // epilogue: C frag rows (g, g+8) = px (wox+g, wox+g+8), cols oc0, oc0+1
    const size_t plane = (size_t)OH * OW;
    int oy = oy0 + ry;
    int ox = wox + g;
    #pragma unroll
    for (int ocg = 0; ocg < OCG; ocg++) {
        int oc0 = (zb + ocg) * 8 + 2 * t;
        float bv0 = bias[oc0], bv1 = bias[oc0 + 1];
        size_t base0 = ((size_t)n * (OCGT * 8) + oc0) * plane + (size_t)oy * OW;
        float v00 = fmaxf(acc[ocg].x + bv0, 0.f);
        float v01 = fmaxf(acc[ocg].y + bv1, 0.f);
        float v10 = fmaxf(acc[ocg].z + bv0, 0.f);
        float v11 = fmaxf(acc[ocg].w + bv1, 0.f);
        if (LAYER == 3) {
            g_m3[base0 + ox]             = v00;
            g_m3[base0 + plane + ox]     = v01;
            g_m3[base0 + ox + 8]         = v10;
            g_m3[base0 + plane + ox + 8] = v11;
        } else if (LAYER == 2) {
            g_m2[base0 + ox]             = __float2bfloat16(v00);
            g_m2[base0 + plane + ox]     = __float2bfloat16(v01);
            g_m2[base0 + ox + 8]         = __float2bfloat16(v10);
            g_m2[base0 + plane + ox + 8] = __float2bfloat16(v11);
        } else {
            g_m1[base0 + ox]             = __float2bfloat16(v00);
            g_m1[base0 + plane + ox]     = __float2bfloat16(v01);
            g_m1[base0 + ox + 8]         = __float2bfloat16(v10);
            g_m1[base0 + plane + ox + 8] = __float2bfloat16(v11);
        }
    }
}

// ---------------- K5: pool + key/qry MLPs + attention softmax ----------------
__global__ void k_attn(const float* __restrict__ k1w, const float* __restrict__ k1b,
                       const float* __restrict__ k2w, const float* __restrict__ k2b,
                       const float* __restrict__ k3w, const float* __restrict__ k3b,
                       const float* __restrict__ q1w, const float* __restrict__ q1b,
                       const float* __restrict__ q2w, const float* __restrict__ q2b,
                       const float* __restrict__ q3w, const float* __restrict__ q3b,
                       const float* __restrict__ aw,  const float* __restrict__ ab) {
    int b = blockIdx.x;
    int tid = threadIdx.x;
    int warp = tid >> 5, lane = tid & 31;
    __shared__ float s_pool[5][64];
    __shared__ float s_key[5][256];
    __shared__ float s_h1[256];
    __shared__ float s_h2[128];
    __shared__ float s_qry[32];
    __shared__ float s_q[256];
    __shared__ float s_log[5];

    for (int tk = warp; tk < 5 * 64; tk += 8) {
        int j = tk >> 6, c = tk & 63;
        const float* p = g_m3 + ((size_t)((b * 5 + j) * 64 + c)) * 512;
        float s = 0.f;
        for (int k = lane; k < 512; k += 32) s += p[k];
        #pragma unroll
        for (int o = 16; o; o >>= 1) s += __shfl_xor_sync(0xFFFFFFFFu, s, o);
        if (lane == 0) s_pool[j][c] = s * (1.0f / 512.0f);
    }
    __syncthreads();

    for (int j = 0; j < 5; j++) {
        {   float a = k1b[tid];
            #pragma unroll 8
            for (int c = 0; c < 64; c++) a += s_pool[j][c] * k1w[tid * 64 + c];
            s_h1[tid] = fmaxf(a, 0.f); }
        __syncthreads();
        if (tid < 128) {
            float a = k2b[tid];
            #pragma unroll 8
            for (int c = 0; c < 256; c++) a += s_h1[c] * k2w[tid * 256 + c];
            s_h2[tid] = fmaxf(a, 0.f);
        }
        __syncthreads();
        {   float a = k3b[tid];
            #pragma unroll 8
            for (int c = 0; c < 128; c++) a += s_h2[c] * k3w[tid * 128 + c];
            s_key[j][tid] = a; }
        __syncthreads();
    }

    {   float a = q1b[tid];
        #pragma unroll 8
        for (int c = 0; c < 64; c++) a += s_pool[0][c] * q1w[tid * 64 + c];
        s_h1[tid] = fmaxf(a, 0.f); }
    __syncthreads();
    if (tid < 128) {
        float a = q2b[tid];
        #pragma unroll 8
        for (int c = 0; c < 256; c++) a += s_h1[c] * q2w[tid * 256 + c];
        s_h2[tid] = fmaxf(a, 0.f);
    }
    __syncthreads();
    if (tid < 32) {
        float a = q3b[tid];
        #pragma unroll 8
        for (int c = 0; c < 128; c++) a += s_h2[c] * q3w[tid * 128 + c];
        s_qry[tid] = a;
    }
    __syncthreads();
    {   float a = ab[tid];
        #pragma unroll
        for (int m = 0; m < 32; m++) a += s_qry[m] * aw[tid * 32 + m];
        s_q[tid] = a; }
    __syncthreads();

    if (warp < 5) {
        float s = 0.f;
        for (int k = lane; k < 256; k += 32) s += s_key[warp][k] * s_q[k];
        #pragma unroll
        for (int o = 16; o; o >>= 1) s += __shfl_xor_sync(0xFFFFFFFFu, s, o);
        if (lane == 0) s_log[warp] = s;
    }
    __syncthreads();
    if (tid == 0) {
        float mx = s_log[0];
        #pragma unroll
        for (int j = 1; j < 5; j++) mx = fmaxf(mx, s_log[j]);
        float e[5], sum = 0.f;
        #pragma unroll
        for (int j = 0; j < 5; j++) { e[j] = __expf(s_log[j] - mx); sum += e[j]; }
        float inv = 1.0f / sum;
        #pragma unroll
        for (int j = 0; j < 5; j++) g_attn[b * 5 + j] = e[j] * inv;
    }
}

// ---------------- K6: streaming attention-weighted fusion (float4, no gathers) ----
__global__ void __launch_bounds__(256) k_fuse(float* __restrict__ out) {
    size_t idx = (size_t)blockIdx.x * 256 + threadIdx.x;   // over float4s
    const size_t per_b = (size_t)CIN * HH * WW / 4;        // 524288
    int b = (int)(idx / per_b);
    size_t r = idx - (size_t)b * per_b;
    float a0 = __ldg(&g_attn[b * 5 + 0]);
    float a1 = __ldg(&g_attn[b * 5 + 1]);
    float a2 = __ldg(&g_attn[b * 5 + 2]);
    float a3 = __ldg(&g_attn[b * 5 + 3]);
    float a4 = __ldg(&g_attn[b * 5 + 4]);
    const float4* base = (const float4*)g_neigh + (size_t)b * 5 * per_b + r;
    float4 v0 = base[0 * per_b], v1 = base[1 * per_b], v2 = base[2 * per_b];
    float4 v3 = base[3 * per_b], v4 = base[4 * per_b];
    float4 o;
    o.x = a0 * v0.x + a1 * v1.x + a2 * v2.x + a3 * v3.x + a4 * v4.x;
    o.y = a0 * v0.y + a1 * v1.y + a2 * v2.y + a3 * v3.y + a4 * v4.y;
    o.z = a0 * v0.z + a1 * v1.z + a2 * v2.z + a3 * v3.z + a4 * v4.z;
    o.w = a0 * v0.w + a1 * v1.w + a2 * v2.w + a3 * v3.w + a4 * v4.w;
    ((float4*)out)[idx] = o;
}

// ---------------- launch ----------------
extern "C" void kernel_launch(void* const* d_in, const int* in_sizes, int n_in,
                              void* d_out, int out_size) {
    const float* x    = (const float*)d_in[0];
    // d_in[1] = record_len (int32) — unused (reference ignores it, all = L)
    const float* nam  = (const float*)d_in[2];
    const float* c1w  = (const float*)d_in[3];
    const float* c1b  = (const float*)d_in[4];
    const float* c2w  = (const float*)d_in[5];
    const float* c2b  = (const float*)d_in[6];
    const float* c3w  = (const float*)d_in[7];
    const float* c3b  = (const float*)d_in[8];
    const float* k1w  = (const float*)d_in[9];
    const float* k1b  = (const float*)d_in[10];
    const float* k2w  = (const float*)d_in[11];
    const float* k2b  = (const float*)d_in[12];
    const float* k3w  = (const float*)d_in[13];
    const float* k3b  = (const float*)d_in[14];
    const float* q1w  = (const float*)d_in[15];
    const float* q1b  = (const float*)d_in[16];
    const float* q2w  = (const float*)d_in[17];
    const float* q2b  = (const float*)d_in[18];
    const float* q3w  = (const float*)d_in[19];
    const float* q3b  = (const float*)d_in[20];
    const float* aw   = (const float*)d_in[21];
    const float* abv  = (const float*)d_in[22];
    float* out = (float*)d_out;

    k_pack<<<128, 256>>>(c1w, c2w, c3w);
    k_gridsample<<<dim3(HH, NN), WW>>>(x, nam);
    //      NTHR IC OCGT OCG  IH   IW ROWS CH LAYER
    k_conv<256, 64,  4,  4, 256, 128,  2,  8, 1><<<dim3(64, NN, 1), 256>>>(c1b);
    k_conv<128, 32,  8,  4, 128,  64,  2,  8, 2><<<dim3(16, NN, 2), 128>>>(c2b);
    k_conv<128, 64,  8,  4,  64,  32,  4,  8, 3><<<dim3( 8, NN, 2), 128>>>(c3b);
    k_attn<<<BB, 256>>>(k1w, k1b, k2w, k2b, k3w, k3b,
                        q1w, q1b, q2w, q2b, q3w, q3b, aw, abv);
    k_fuse<<<(int)((size_t)BB * CIN * HH * WW / 4 / 256), 256>>>(out);
}